// round 4
// baseline (speedup 1.0000x reference)
#include <cuda_runtime.h>
#include <math.h>

#define BDIM 128
#define NDIM 20000
#define DDIM 3072
#define KB 16
#define NSPLIT 8
#define NCHUNK (NDIM / NSPLIT)        /* 2500 */
#define NTILES ((NDIM + 127) / 128)   /* 157 */
#define DTILES (DDIM / 128)           /* 24 */

// Scratch (allocation-free rule: __device__ globals)
__device__ float g_s[BDIM * NDIM];               // scaled logits, 10.24 MB
__device__ float g_rowmax[BDIM];
__device__ float g_rowsum[BDIM];
__device__ float g_part[NSPLIT * BDIM * DDIM];   // GEMM2 split-K partials, 12.6 MB

// ---- packed fp32x2 helpers (Blackwell FFMA2 — ptxas never emits this from C++)
__device__ __forceinline__ void ffma2(unsigned long long& acc,
                                      unsigned long long a,
                                      unsigned long long b)
{
    asm("fma.rn.f32x2 %0, %1, %2, %0;" : "+l"(acc) : "l"(a), "l"(b));
}
__device__ __forceinline__ unsigned long long rep2(float v)
{
    unsigned long long r;
    unsigned int u = __float_as_uint(v);
    asm("mov.b64 %0, {%1, %1};" : "=l"(r) : "r"(u));
    return r;
}
__device__ __forceinline__ float2 unpack2(unsigned long long v)
{
    float2 f;
    asm("mov.b64 {%0, %1}, %2;" : "=f"(f.x), "=f"(f.y) : "l"(v));
    return f;
}

// ---------------------------------------------------------------------------
// GEMM1: s[b,n] = alpha[b] * (x_b . gt_n) - beta[b] * ||gt_n||^2
// 128x128 tile, 8x8 microtile, accumulators packed f32x2 along b-rows.
// ---------------------------------------------------------------------------
__global__ __launch_bounds__(256) void gemm1_kernel(const float* __restrict__ x,
                                                    const float* __restrict__ t,
                                                    const float* __restrict__ gt)
{
    __shared__ float As[KB][BDIM];   // x transposed: As[k][b]
    __shared__ float Bs[KB][BDIM];   // gt transposed: Bs[k][n]
    __shared__ float g2s[BDIM];

    const int tid  = threadIdx.x;
    const int nblk = blockIdx.x * 128;
    const int r0 = (tid >> 4) << 3;     // output row group (b)
    const int c0 = (tid & 15) << 3;     // output col group (n)

    const int lrow = tid >> 2;          // 0..63 (loads rows lrow, lrow+64)
    const int lk   = (tid & 3) << 2;    // 0,4,8,12

    unsigned long long acc2[4][8];      // rows (r0+2i, r0+2i+1) x col j
#pragma unroll
    for (int i = 0; i < 4; i++)
#pragma unroll
        for (int j = 0; j < 8; j++) acc2[i][j] = 0ULL;
    float g2a[8] = {0, 0, 0, 0, 0, 0, 0, 0};

    const float* xr0 = x + (size_t)lrow * DDIM + lk;
    const float* xr1 = x + (size_t)(lrow + 64) * DDIM + lk;
    const int n0g = nblk + lrow;
    const int n1g = nblk + lrow + 64;
    const float* gr0 = gt + (size_t)n0g * DDIM + lk;
    const float* gr1 = gt + (size_t)n1g * DDIM + lk;
    const bool v0 = (n0g < NDIM);
    const bool v1 = (n1g < NDIM);
    const float4 zero4 = make_float4(0.f, 0.f, 0.f, 0.f);

    for (int k0 = 0; k0 < DDIM; k0 += KB) {
        float4 a0 = *(const float4*)(xr0 + k0);
        float4 a1 = *(const float4*)(xr1 + k0);
        float4 b0 = v0 ? *(const float4*)(gr0 + k0) : zero4;
        float4 b1 = v1 ? *(const float4*)(gr1 + k0) : zero4;

        __syncthreads();
        As[lk + 0][lrow] = a0.x; As[lk + 1][lrow] = a0.y;
        As[lk + 2][lrow] = a0.z; As[lk + 3][lrow] = a0.w;
        As[lk + 0][lrow + 64] = a1.x; As[lk + 1][lrow + 64] = a1.y;
        As[lk + 2][lrow + 64] = a1.z; As[lk + 3][lrow + 64] = a1.w;
        Bs[lk + 0][lrow] = b0.x; Bs[lk + 1][lrow] = b0.y;
        Bs[lk + 2][lrow] = b0.z; Bs[lk + 3][lrow] = b0.w;
        Bs[lk + 0][lrow + 64] = b1.x; Bs[lk + 1][lrow + 64] = b1.y;
        Bs[lk + 2][lrow + 64] = b1.z; Bs[lk + 3][lrow + 64] = b1.w;
        __syncthreads();

#pragma unroll
        for (int k = 0; k < KB; k++) {
            unsigned long long a2[4];
            float b[8];
#pragma unroll
            for (int i = 0; i < 4; i++)
                a2[i] = *(const unsigned long long*)&As[k][r0 + 2 * i];
#pragma unroll
            for (int j = 0; j < 8; j++) b[j] = Bs[k][c0 + j];
            if (tid < 16) {          // r0==0 threads own each n-column once
#pragma unroll
                for (int j = 0; j < 8; j++) g2a[j] += b[j] * b[j];
            }
            unsigned long long bb[8];
#pragma unroll
            for (int j = 0; j < 8; j++) bb[j] = rep2(b[j]);
#pragma unroll
            for (int i = 0; i < 4; i++)
#pragma unroll
                for (int j = 0; j < 8; j++) ffma2(acc2[i][j], a2[i], bb[j]);
        }
    }

    if (tid < 16) {
#pragma unroll
        for (int j = 0; j < 8; j++) g2s[c0 + j] = g2a[j];
    }
    __syncthreads();

    float g2l[8];
#pragma unroll
    for (int j = 0; j < 8; j++) g2l[j] = g2s[c0 + j];

#pragma unroll
    for (int i = 0; i < 4; i++) {
#pragma unroll
        for (int jj = 0; jj < 2; jj++) {
            const int b = r0 + 2 * i + jj;
            const float tt  = t[b] * (1.0f / 999.0f);
            const float sg  = 1.0f - tt;
            const float inv = 1.0f / (sg * sg);
            const float alpha = tt * inv;
            const float beta  = 0.5f * tt * tt * inv;
#pragma unroll
            for (int j = 0; j < 8; j++) {
                const int n = nblk + c0 + j;
                if (n < NDIM) {
                    float2 p = unpack2(acc2[i][j]);
                    const float v = jj ? p.y : p.x;
                    g_s[b * NDIM + n] = alpha * v - beta * g2l[j];
                }
            }
        }
    }
}

// ---------------------------------------------------------------------------
// Per-row softmax stats: rowmax and sum(exp(s - rowmax)). One block per row.
// ---------------------------------------------------------------------------
__global__ __launch_bounds__(256) void softmax_stats_kernel()
{
    const int b   = blockIdx.x;
    const int tid = threadIdx.x;
    const float* row = g_s + (size_t)b * NDIM;
    __shared__ float red[256];

    float m = -INFINITY;
    for (int i = tid; i < NDIM; i += 256) m = fmaxf(m, row[i]);
    red[tid] = m;
    __syncthreads();
    for (int s = 128; s > 0; s >>= 1) {
        if (tid < s) red[tid] = fmaxf(red[tid], red[tid + s]);
        __syncthreads();
    }
    m = red[0];
    __syncthreads();

    float sum = 0.0f;
    for (int i = tid; i < NDIM; i += 256) sum += __expf(row[i] - m);
    red[tid] = sum;
    __syncthreads();
    for (int s = 128; s > 0; s >>= 1) {
        if (tid < s) red[tid] += red[tid + s];
        __syncthreads();
    }
    if (tid == 0) {
        g_rowmax[b] = m;
        g_rowsum[b] = red[0];
    }
}

// ---------------------------------------------------------------------------
// GEMM2: partial[b,d] = sum_{n in split} eta[b,n] * gt[n,d]
// eta materialized on the fly from g_s. Split-K over N into NSPLIT partials.
// Accumulators packed f32x2 along b-rows.
// ---------------------------------------------------------------------------
__global__ __launch_bounds__(256) void gemm2_kernel(const float* __restrict__ gt)
{
    __shared__ float Es[KB][BDIM];   // eta transposed: Es[kn][b]
    __shared__ float Gs[KB][BDIM];   // gt tile: Gs[kn][d]

    const int tid  = threadIdx.x;
    const int dblk = blockIdx.x * 128;
    const int nbeg = blockIdx.y * NCHUNK;
    const int nend = nbeg + NCHUNK;
    const int r0 = (tid >> 4) << 3;
    const int c0 = (tid & 15) << 3;

    // eta loads: rows lrow, lrow+64 (b); 4 n's at lk
    const int lrow = tid >> 2;
    const int lk   = (tid & 3) << 2;
    // gt loads: rows gn, gn+8 (n); float4 at gd
    const int gn = tid >> 5;            // 0..7
    const int gd = (tid & 31) << 2;     // 0..124

    const float m0  = g_rowmax[lrow];
    const float is0 = 1.0f / g_rowsum[lrow];
    const float m1  = g_rowmax[lrow + 64];
    const float is1 = 1.0f / g_rowsum[lrow + 64];

    const float4 zero4 = make_float4(0.f, 0.f, 0.f, 0.f);

    unsigned long long acc2[4][8];
#pragma unroll
    for (int i = 0; i < 4; i++)
#pragma unroll
        for (int j = 0; j < 8; j++) acc2[i][j] = 0ULL;

    for (int n0 = nbeg; n0 < nend; n0 += KB) {
        // eta tile (scalar guarded loads; g_s is L2-resident)
        float e0[4], e1[4];
#pragma unroll
        for (int c = 0; c < 4; c++) {
            const int n = n0 + lk + c;
            if (n < nend) {
                e0[c] = __expf(g_s[lrow * NDIM + n] - m0) * is0;
                e1[c] = __expf(g_s[(lrow + 64) * NDIM + n] - m1) * is1;
            } else {
                e0[c] = 0.0f;
                e1[c] = 0.0f;
            }
        }
        // gt tile
        const int nr0 = n0 + gn, nr1 = n0 + gn + 8;
        float4 gv0 = (nr0 < nend) ? *(const float4*)(gt + (size_t)nr0 * DDIM + dblk + gd) : zero4;
        float4 gv1 = (nr1 < nend) ? *(const float4*)(gt + (size_t)nr1 * DDIM + dblk + gd) : zero4;

        __syncthreads();
#pragma unroll
        for (int c = 0; c < 4; c++) {
            Es[lk + c][lrow]      = e0[c];
            Es[lk + c][lrow + 64] = e1[c];
        }
        Gs[gn][gd + 0] = gv0.x; Gs[gn][gd + 1] = gv0.y;
        Gs[gn][gd + 2] = gv0.z; Gs[gn][gd + 3] = gv0.w;
        Gs[gn + 8][gd + 0] = gv1.x; Gs[gn + 8][gd + 1] = gv1.y;
        Gs[gn + 8][gd + 2] = gv1.z; Gs[gn + 8][gd + 3] = gv1.w;
        __syncthreads();

#pragma unroll
        for (int k = 0; k < KB; k++) {
            unsigned long long a2[4];
            float b[8];
#pragma unroll
            for (int i = 0; i < 4; i++)
                a2[i] = *(const unsigned long long*)&Es[k][r0 + 2 * i];
#pragma unroll
            for (int j = 0; j < 8; j++) b[j] = Gs[k][c0 + j];
            unsigned long long bb[8];
#pragma unroll
            for (int j = 0; j < 8; j++) bb[j] = rep2(b[j]);
#pragma unroll
            for (int i = 0; i < 4; i++)
#pragma unroll
                for (int j = 0; j < 8; j++) ffma2(acc2[i][j], a2[i], bb[j]);
        }
    }

    float* outp = g_part + (size_t)blockIdx.y * BDIM * DDIM;
#pragma unroll
    for (int i = 0; i < 4; i++)
#pragma unroll
        for (int j = 0; j < 8; j++) {
            float2 p = unpack2(acc2[i][j]);
            outp[(r0 + 2 * i + 0) * DDIM + dblk + c0 + j] = p.x;
            outp[(r0 + 2 * i + 1) * DDIM + dblk + c0 + j] = p.y;
        }
}

// ---------------------------------------------------------------------------
// Epilogue: out = (sum_splits partial - x) / sig
// ---------------------------------------------------------------------------
__global__ __launch_bounds__(256) void epilogue_kernel(const float* __restrict__ x,
                                                       const float* __restrict__ t,
                                                       float* __restrict__ out)
{
    const int idx = blockIdx.x * 256 + threadIdx.x;
    if (idx >= BDIM * DDIM) return;
    const int b = idx / DDIM;
    float a = 0.0f;
#pragma unroll
    for (int s = 0; s < NSPLIT; s++) a += g_part[(size_t)s * BDIM * DDIM + idx];
    const float tt = t[b] * (1.0f / 999.0f);
    const float sg = 1.0f - tt;
    out[idx] = (a - x[idx]) / sg;
}

extern "C" void kernel_launch(void* const* d_in, const int* in_sizes, int n_in,
                              void* d_out, int out_size)
{
    const float* xt = (const float*)d_in[0];
    const float* t  = (const float*)d_in[1];
    const float* gt = (const float*)d_in[2];
    float* out = (float*)d_out;

    gemm1_kernel<<<NTILES, 256>>>(xt, t, gt);
    softmax_stats_kernel<<<BDIM, 256>>>();
    dim3 g3(DTILES, NSPLIT);
    gemm2_kernel<<<g3, 256>>>(gt);
    epilogue_kernel<<<(BDIM * DDIM + 255) / 256, 256>>>(xt, t, out);
}

// round 5
// speedup vs baseline: 1.5022x; 1.5022x over previous
#include <cuda_runtime.h>
#include <cuda_bf16.h>
#include <math.h>
#include <stdint.h>

#define BDIM 128
#define NDIM 20000
#define DDIM 3072
#define KB 16
#define NSPLIT 8
#define NCHUNK (NDIM / NSPLIT)        /* 2500 */
#define NTILES ((NDIM + 127) / 128)   /* 157 */
#define DTILES (DDIM / 128)           /* 24 */
#define LDA 24                        /* padded smem row (bf16 elems) */

// Scratch (allocation-free rule: __device__ globals)
__device__ float g_s[BDIM * NDIM];               // scaled logits, 10.24 MB
__device__ float g_rowmax[BDIM];
__device__ float g_rowsum[BDIM];
__device__ float g_part[NSPLIT * BDIM * DDIM];   // GEMM2 split-K partials

// ---------------- helpers ----------------
__device__ __forceinline__ float bfround(float v)
{
    return __bfloat162float(__float2bfloat16(v));
}
__device__ __forceinline__ uint32_t pk2(float a, float b)
{
    __nv_bfloat162 t = __floats2bfloat162_rn(a, b);
    return *reinterpret_cast<uint32_t*>(&t);
}
__device__ __forceinline__ void mma16816(float c[4], const uint32_t a[4], const uint32_t b[2])
{
    asm volatile(
        "mma.sync.aligned.m16n8k16.row.col.f32.bf16.bf16.f32 "
        "{%0,%1,%2,%3}, {%4,%5,%6,%7}, {%8,%9}, {%0,%1,%2,%3};"
        : "+f"(c[0]), "+f"(c[1]), "+f"(c[2]), "+f"(c[3])
        : "r"(a[0]), "r"(a[1]), "r"(a[2]), "r"(a[3]), "r"(b[0]), "r"(b[1]));
}

// One pass over a (A,B) smem buffer pair: 64x32 warp tile, k=16.
__device__ __forceinline__ void mma_pass(const __nv_bfloat16* __restrict__ A,
                                         const __nv_bfloat16* __restrict__ B,
                                         float c[4][4][4], int wm, int wn, int lane)
{
    const int k0 = (lane & 3) * 2;
    const int rr = lane >> 2;
    uint32_t bf[4][2];
#pragma unroll
    for (int nt = 0; nt < 4; nt++) {
        const int col = wn + nt * 8 + rr;
        bf[nt][0] = *(const uint32_t*)&B[col * LDA + k0];
        bf[nt][1] = *(const uint32_t*)&B[col * LDA + k0 + 8];
    }
#pragma unroll
    for (int mt = 0; mt < 4; mt++) {
        const int row = wm + mt * 16 + rr;
        uint32_t a[4];
        a[0] = *(const uint32_t*)&A[row * LDA + k0];
        a[1] = *(const uint32_t*)&A[(row + 8) * LDA + k0];
        a[2] = *(const uint32_t*)&A[row * LDA + k0 + 8];
        a[3] = *(const uint32_t*)&A[(row + 8) * LDA + k0 + 8];
#pragma unroll
        for (int nt = 0; nt < 4; nt++) mma16816(c[mt][nt], a, bf[nt]);
    }
}

// 3-way split of 8 floats -> three uint4 (8 bf16 each)
__device__ __forceinline__ void split3_store(const float v[8], __nv_bfloat16* Ph,
                                             __nv_bfloat16* Pm, __nv_bfloat16* Pl, int off)
{
    float h[8], m[8], l[8];
#pragma unroll
    for (int i = 0; i < 8; i++) {
        h[i] = bfround(v[i]);
        float rm = v[i] - h[i];
        m[i] = bfround(rm);
        l[i] = rm - m[i];
    }
    uint4 uh, um, ul;
    uh.x = pk2(h[0], h[1]); uh.y = pk2(h[2], h[3]); uh.z = pk2(h[4], h[5]); uh.w = pk2(h[6], h[7]);
    um.x = pk2(m[0], m[1]); um.y = pk2(m[2], m[3]); um.z = pk2(m[4], m[5]); um.w = pk2(m[6], m[7]);
    ul.x = pk2(l[0], l[1]); ul.y = pk2(l[2], l[3]); ul.z = pk2(l[4], l[5]); ul.w = pk2(l[6], l[7]);
    *(uint4*)&Ph[off] = uh;
    *(uint4*)&Pm[off] = um;
    *(uint4*)&Pl[off] = ul;
}

// 2-way split of 8 floats -> two uint4
__device__ __forceinline__ void split2_store(const float v[8], __nv_bfloat16* Ph,
                                             __nv_bfloat16* Pl, int off)
{
    float h[8], l[8];
#pragma unroll
    for (int i = 0; i < 8; i++) {
        h[i] = bfround(v[i]);
        l[i] = v[i] - h[i];
    }
    uint4 uh, ul;
    uh.x = pk2(h[0], h[1]); uh.y = pk2(h[2], h[3]); uh.z = pk2(h[4], h[5]); uh.w = pk2(h[6], h[7]);
    ul.x = pk2(l[0], l[1]); ul.y = pk2(l[2], l[3]); ul.z = pk2(l[4], l[5]); ul.w = pk2(l[6], l[7]);
    *(uint4*)&Ph[off] = uh;
    *(uint4*)&Pl[off] = ul;
}

// ---------------------------------------------------------------------------
// GEMM1: logits s[b,n] = alpha[b]*(x_b . gt_n) - beta[b]*||gt_n||^2
// bf16 tensor-core, 3-way split x 3-way split, 6 passes. 128x128 CTA tile.
// ---------------------------------------------------------------------------
__global__ __launch_bounds__(256) void gemm1_kernel(const float* __restrict__ x,
                                                    const float* __restrict__ t,
                                                    const float* __restrict__ gt)
{
    __shared__ __nv_bfloat16 Ah[128 * LDA], Am[128 * LDA], Al[128 * LDA];
    __shared__ __nv_bfloat16 Bh[128 * LDA], Bm[128 * LDA], Bl[128 * LDA];
    __shared__ float alpha_s[128], beta_s[128], g2s[128];

    const int tid = threadIdx.x;
    const int lane = tid & 31;
    const int warp = tid >> 5;
    const int wm = (warp >> 2) * 64;
    const int wn = (warp & 3) * 32;
    const int nblk = blockIdx.x * 128;

    if (tid < 128) {
        const float tt = t[tid] * (1.0f / 999.0f);
        const float sg = 1.0f - tt;
        const float inv = 1.0f / (sg * sg);
        alpha_s[tid] = tt * inv;
        beta_s[tid] = 0.5f * tt * tt * inv;
    }

    const int r = tid >> 1;
    const int c8 = (tid & 1) * 8;
    const int soff = r * LDA + c8;
    const float* xp = x + (size_t)r * DDIM + c8;
    const int gn = nblk + r;
    const bool gv = (gn < NDIM);
    const float* gp = gt + (size_t)gn * DDIM + c8;

    float c[4][4][4];
#pragma unroll
    for (int a = 0; a < 4; a++)
#pragma unroll
        for (int b = 0; b < 4; b++)
#pragma unroll
            for (int e = 0; e < 4; e++) c[a][b][e] = 0.0f;

    float g2acc = 0.0f;
    float xv[8], gvv[8];
    {
        float4 a0 = *(const float4*)(xp);
        float4 a1 = *(const float4*)(xp + 4);
        xv[0] = a0.x; xv[1] = a0.y; xv[2] = a0.z; xv[3] = a0.w;
        xv[4] = a1.x; xv[5] = a1.y; xv[6] = a1.z; xv[7] = a1.w;
        if (gv) {
            float4 b0 = *(const float4*)(gp);
            float4 b1 = *(const float4*)(gp + 4);
            gvv[0] = b0.x; gvv[1] = b0.y; gvv[2] = b0.z; gvv[3] = b0.w;
            gvv[4] = b1.x; gvv[5] = b1.y; gvv[6] = b1.z; gvv[7] = b1.w;
        } else {
#pragma unroll
            for (int i = 0; i < 8; i++) gvv[i] = 0.0f;
        }
    }

    for (int k0 = 0; k0 < DDIM; k0 += KB) {
        split3_store(xv, Ah, Am, Al, soff);
        split3_store(gvv, Bh, Bm, Bl, soff);
#pragma unroll
        for (int i = 0; i < 8; i++) g2acc += gvv[i] * gvv[i];
        __syncthreads();

        if (k0 + KB < DDIM) {
            float4 a0 = *(const float4*)(xp + k0 + KB);
            float4 a1 = *(const float4*)(xp + k0 + KB + 4);
            xv[0] = a0.x; xv[1] = a0.y; xv[2] = a0.z; xv[3] = a0.w;
            xv[4] = a1.x; xv[5] = a1.y; xv[6] = a1.z; xv[7] = a1.w;
            if (gv) {
                float4 b0 = *(const float4*)(gp + k0 + KB);
                float4 b1 = *(const float4*)(gp + k0 + KB + 4);
                gvv[0] = b0.x; gvv[1] = b0.y; gvv[2] = b0.z; gvv[3] = b0.w;
                gvv[4] = b1.x; gvv[5] = b1.y; gvv[6] = b1.z; gvv[7] = b1.w;
            }
        }

        mma_pass(Ah, Bh, c, wm, wn, lane);
        mma_pass(Ah, Bm, c, wm, wn, lane);
        mma_pass(Am, Bh, c, wm, wn, lane);
        mma_pass(Ah, Bl, c, wm, wn, lane);
        mma_pass(Am, Bm, c, wm, wn, lane);
        mma_pass(Al, Bh, c, wm, wn, lane);
        __syncthreads();
    }

    g2acc += __shfl_xor_sync(0xffffffffu, g2acc, 1);
    if ((tid & 1) == 0) g2s[r] = g2acc;
    __syncthreads();

#pragma unroll
    for (int mt = 0; mt < 4; mt++) {
#pragma unroll
        for (int nt = 0; nt < 4; nt++) {
#pragma unroll
            for (int e = 0; e < 4; e++) {
                const int row = wm + mt * 16 + (lane >> 2) + ((e & 2) ? 8 : 0);
                const int col = wn + nt * 8 + (lane & 3) * 2 + (e & 1);
                const int n = nblk + col;
                if (n < NDIM)
                    g_s[row * NDIM + n] = alpha_s[row] * c[mt][nt][e] - beta_s[row] * g2s[col];
            }
        }
    }
}

// ---------------------------------------------------------------------------
// Per-row softmax stats
// ---------------------------------------------------------------------------
__global__ __launch_bounds__(256) void softmax_stats_kernel()
{
    const int b = blockIdx.x;
    const int tid = threadIdx.x;
    const float* row = g_s + (size_t)b * NDIM;
    __shared__ float red[256];

    float m = -INFINITY;
    for (int i = tid; i < NDIM; i += 256) m = fmaxf(m, row[i]);
    red[tid] = m;
    __syncthreads();
    for (int s = 128; s > 0; s >>= 1) {
        if (tid < s) red[tid] = fmaxf(red[tid], red[tid + s]);
        __syncthreads();
    }
    m = red[0];
    __syncthreads();

    float sum = 0.0f;
    for (int i = tid; i < NDIM; i += 256) sum += __expf(row[i] - m);
    red[tid] = sum;
    __syncthreads();
    for (int s = 128; s > 0; s >>= 1) {
        if (tid < s) red[tid] += red[tid + s];
        __syncthreads();
    }
    if (tid == 0) {
        g_rowmax[b] = m;
        g_rowsum[b] = red[0];
    }
}

// ---------------------------------------------------------------------------
// GEMM2: partial[b,d] = sum_{n in chunk} eta[b,n] * gt[n,d]
// bf16 tensor-core, 2-way split both operands, 3 passes. 128x128 CTA tile.
// ---------------------------------------------------------------------------
__global__ __launch_bounds__(256) void gemm2_kernel(const float* __restrict__ gt)
{
    __shared__ __nv_bfloat16 Eh[128 * LDA], El[128 * LDA];
    __shared__ __nv_bfloat16 Gh[128 * LDA], Gl[128 * LDA];

    const int tid = threadIdx.x;
    const int lane = tid & 31;
    const int warp = tid >> 5;
    const int wm = (warp >> 2) * 64;
    const int wn = (warp & 3) * 32;
    const int dblk = blockIdx.x * 128;
    const int nbeg = blockIdx.y * NCHUNK;
    const int nend = nbeg + NCHUNK;

    // eta producer mapping
    const int r = tid >> 1;
    const int c8 = (tid & 1) * 8;
    const float m_r = g_rowmax[r];
    const float is_r = 1.0f / g_rowsum[r];
    const float* sp = g_s + (size_t)r * NDIM;

    // gt producer mapping (transposed store)
    const int tn = tid & 15;
    const int td8 = (tid >> 4) * 8;

    float c[4][4][4];
#pragma unroll
    for (int a = 0; a < 4; a++)
#pragma unroll
        for (int b = 0; b < 4; b++)
#pragma unroll
            for (int e = 0; e < 4; e++) c[a][b][e] = 0.0f;

    float sv[8], gvv[8];
    // initial raw loads (n0 = nbeg)
    {
        const int n0 = nbeg;
#pragma unroll
        for (int i = 0; i < 8; i++) {
            const int n = n0 + c8 + i;
            sv[i] = (n < nend) ? sp[n] : -INFINITY;
        }
        const int gn = n0 + tn;
        if (gn < nend) {
            const float* gp = gt + (size_t)gn * DDIM + dblk + td8;
            float4 b0 = *(const float4*)(gp);
            float4 b1 = *(const float4*)(gp + 4);
            gvv[0] = b0.x; gvv[1] = b0.y; gvv[2] = b0.z; gvv[3] = b0.w;
            gvv[4] = b1.x; gvv[5] = b1.y; gvv[6] = b1.z; gvv[7] = b1.w;
        } else {
#pragma unroll
            for (int i = 0; i < 8; i++) gvv[i] = 0.0f;
        }
    }

    for (int n0 = nbeg; n0 < nend; n0 += KB) {
        // eta = exp(s - m)/sum, split 2-way
        float ev[8];
#pragma unroll
        for (int i = 0; i < 8; i++)
            ev[i] = (sv[i] == -INFINITY) ? 0.0f : __expf(sv[i] - m_r) * is_r;
        split2_store(ev, Eh, El, r * LDA + c8);

        // gt split 2-way, transposed store [d][k]
        {
            float h, l;
#pragma unroll
            for (int i = 0; i < 8; i++) {
                h = bfround(gvv[i]);
                l = gvv[i] - h;
                Gh[(td8 + i) * LDA + tn] = __float2bfloat16(h);
                Gl[(td8 + i) * LDA + tn] = __float2bfloat16(l);
            }
        }
        __syncthreads();

        // prefetch next raw tiles
        if (n0 + KB < nend) {
            const int nn = n0 + KB;
#pragma unroll
            for (int i = 0; i < 8; i++) {
                const int n = nn + c8 + i;
                sv[i] = (n < nend) ? sp[n] : -INFINITY;
            }
            const int gn = nn + tn;
            if (gn < nend) {
                const float* gp = gt + (size_t)gn * DDIM + dblk + td8;
                float4 b0 = *(const float4*)(gp);
                float4 b1 = *(const float4*)(gp + 4);
                gvv[0] = b0.x; gvv[1] = b0.y; gvv[2] = b0.z; gvv[3] = b0.w;
                gvv[4] = b1.x; gvv[5] = b1.y; gvv[6] = b1.z; gvv[7] = b1.w;
            } else {
#pragma unroll
                for (int i = 0; i < 8; i++) gvv[i] = 0.0f;
            }
        }

        mma_pass(Eh, Gh, c, wm, wn, lane);
        mma_pass(Eh, Gl, c, wm, wn, lane);
        mma_pass(El, Gh, c, wm, wn, lane);
        __syncthreads();
    }

    float* outp = g_part + (size_t)blockIdx.y * BDIM * DDIM;
#pragma unroll
    for (int mt = 0; mt < 4; mt++) {
#pragma unroll
        for (int nt = 0; nt < 4; nt++) {
            const int row0 = wm + mt * 16 + (lane >> 2);
            const int col = dblk + wn + nt * 8 + (lane & 3) * 2;
            *(float2*)&outp[row0 * DDIM + col] = make_float2(c[mt][nt][0], c[mt][nt][1]);
            *(float2*)&outp[(row0 + 8) * DDIM + col] = make_float2(c[mt][nt][2], c[mt][nt][3]);
        }
    }
}

// ---------------------------------------------------------------------------
// Epilogue: out = (sum_splits partial - x) / sig
// ---------------------------------------------------------------------------
__global__ __launch_bounds__(256) void epilogue_kernel(const float* __restrict__ x,
                                                       const float* __restrict__ t,
                                                       float* __restrict__ out)
{
    const int idx = blockIdx.x * 256 + threadIdx.x;
    if (idx >= BDIM * DDIM) return;
    const int b = idx / DDIM;
    float a = 0.0f;
#pragma unroll
    for (int s = 0; s < NSPLIT; s++) a += g_part[(size_t)s * BDIM * DDIM + idx];
    const float tt = t[b] * (1.0f / 999.0f);
    const float sg = 1.0f - tt;
    out[idx] = (a - x[idx]) / sg;
}

extern "C" void kernel_launch(void* const* d_in, const int* in_sizes, int n_in,
                              void* d_out, int out_size)
{
    const float* xt = (const float*)d_in[0];
    const float* t  = (const float*)d_in[1];
    const float* gt = (const float*)d_in[2];
    float* out = (float*)d_out;

    gemm1_kernel<<<NTILES, 256>>>(xt, t, gt);
    softmax_stats_kernel<<<BDIM, 256>>>();
    dim3 g3(DTILES, NSPLIT);
    gemm2_kernel<<<g3, 256>>>(gt);
    epilogue_kernel<<<(BDIM * DDIM + 255) / 256, 256>>>(xt, t, out);
}

// round 7
// speedup vs baseline: 2.1996x; 1.4642x over previous
#include <cuda_runtime.h>
#include <cuda_bf16.h>
#include <math.h>
#include <stdint.h>

#define NDIM 20000
#define DDIM 3072
#define BDIM 128
#define KB 32
#define CH1 (DDIM / KB)            /* 96 */
#define NT1 ((NDIM + 63) / 64)     /* 313 */
#define NSPLIT 5
#define SPAN2 4000                 /* 20000/5, 125 chunks of 32 */
#define CH2 (SPAN2 / KB)           /* 125 */
#define DT2 (DDIM / 64)            /* 48 */

// GEMM1 smem: per buffer 3 A-splits (128x32 bf16 = 8KB) + 3 B-splits (64x32 = 4KB)
#define SA1(s, p) ((p) * 36864 + (s) * 8192)
#define SB1(s, p) ((p) * 36864 + 24576 + (s) * 4096)
#define SM1_TOTAL (2 * 36864)
// GEMM2 smem: per buffer 2 E-splits (8KB) + 2 G-splits (4KB)
#define SE2(s, p) ((p) * 24576 + (s) * 8192)
#define SG2(s, p) ((p) * 24576 + 16384 + (s) * 4096)
#define SM2_TOTAL (2 * 24576)

// Scratch (allocation-free rule: __device__ globals)
__device__ float g_s[BDIM * NDIM];
__device__ float g_rowsum[BDIM];
__device__ __nv_bfloat16 g_eh[BDIM * NDIM];
__device__ __nv_bfloat16 g_el[BDIM * NDIM];
__device__ float g_part[NSPLIT * BDIM * DDIM];

// Swizzled byte offset inside a [rows x 32k] bf16 tile (row stride 64B).
// 16B group index XOR'd with row bits -> conflict-free STS.128 and frag LDS.32.
__device__ __forceinline__ int toff(int row, int k)
{
    return row * 64 + ((((k >> 3) & 3) ^ ((row >> 1) & 3)) << 4) + ((k * 2) & 15);
}

__device__ __forceinline__ float bfround(float v) { return __bfloat162float(__float2bfloat16(v)); }
__device__ __forceinline__ uint32_t pk2(float a, float b)
{
    __nv_bfloat162 t = __floats2bfloat162_rn(a, b);
    return *reinterpret_cast<uint32_t*>(&t);
}
__device__ __forceinline__ void split3_u4(const float v[8], uint4& uh, uint4& um, uint4& ul)
{
    float h[8], m[8], l[8];
#pragma unroll
    for (int i = 0; i < 8; i++) {
        h[i] = bfround(v[i]);
        float rm = v[i] - h[i];
        m[i] = bfround(rm);
        l[i] = rm - m[i];
    }
    uh = make_uint4(pk2(h[0], h[1]), pk2(h[2], h[3]), pk2(h[4], h[5]), pk2(h[6], h[7]));
    um = make_uint4(pk2(m[0], m[1]), pk2(m[2], m[3]), pk2(m[4], m[5]), pk2(m[6], m[7]));
    ul = make_uint4(pk2(l[0], l[1]), pk2(l[2], l[3]), pk2(l[4], l[5]), pk2(l[6], l[7]));
}
__device__ __forceinline__ void mma16816(float c[4], const uint32_t a[4], const uint32_t b[2])
{
    asm volatile(
        "mma.sync.aligned.m16n8k16.row.col.f32.bf16.bf16.f32 "
        "{%0,%1,%2,%3}, {%4,%5,%6,%7}, {%8,%9}, {%0,%1,%2,%3};"
        : "+f"(c[0]), "+f"(c[1]), "+f"(c[2]), "+f"(c[3])
        : "r"(a[0]), "r"(a[1]), "r"(a[2]), "r"(a[3]), "r"(b[0]), "r"(b[1]));
}

// ---------------------------------------------------------------------------
// GEMM1: s[b,n] = alpha[b]*(x_b.gt_n) - beta[b]*||gt_n||^2
// CTA tile 128b x 64n, KB=32, double-buffered, 6 split passes (3x3, as+bs<3).
// ---------------------------------------------------------------------------
__global__ __launch_bounds__(256, 2) void gemm1_kernel(const float* __restrict__ x,
                                                       const float* __restrict__ t,
                                                       const float* __restrict__ gt)
{
    extern __shared__ char sm[];
    __shared__ float alpha_s[128], beta_s[128], g2s[64];

    const int tid = threadIdx.x, lane = tid & 31, warp = tid >> 5;
    const int wm = (warp & 3) * 32, wn = (warp >> 2) * 32;
    const int nblk = blockIdx.x * 64;

    if (tid < 128) {
        const float tt = t[tid] * (1.0f / 999.0f);
        const float sg = 1.0f - tt;
        const float inv = 1.0f / (sg * sg);
        alpha_s[tid] = tt * inv;
        beta_s[tid] = 0.5f * tt * tt * inv;
    }

    // producer roles
    const int ar = tid >> 1, akh = (tid & 1) * 16;     // x: row ar, k [akh, akh+16)
    const int br = tid >> 2, bk8 = (tid & 3) * 8;      // gt: row br, k [bk8, bk8+8)
    const int gn = nblk + br;
    const bool gvalid = (gn < NDIM);
    const float* xp = x + (size_t)ar * DDIM + akh;
    const float* gp = gt + (size_t)gn * DDIM + bk8;

    float acc[2][4][4];
#pragma unroll
    for (int a = 0; a < 2; a++)
#pragma unroll
        for (int b = 0; b < 4; b++)
#pragma unroll
            for (int e = 0; e < 4; e++) acc[a][b][e] = 0.0f;
    float g2a = 0.0f;
    float xv[16], gv[8];

#define LOAD_G1(kc)                                                        \
    do {                                                                   \
        float4 _a0 = *(const float4*)(xp + (kc));                          \
        float4 _a1 = *(const float4*)(xp + (kc) + 4);                      \
        float4 _a2 = *(const float4*)(xp + (kc) + 8);                      \
        float4 _a3 = *(const float4*)(xp + (kc) + 12);                     \
        xv[0]=_a0.x; xv[1]=_a0.y; xv[2]=_a0.z; xv[3]=_a0.w;                \
        xv[4]=_a1.x; xv[5]=_a1.y; xv[6]=_a1.z; xv[7]=_a1.w;                \
        xv[8]=_a2.x; xv[9]=_a2.y; xv[10]=_a2.z; xv[11]=_a2.w;              \
        xv[12]=_a3.x; xv[13]=_a3.y; xv[14]=_a3.z; xv[15]=_a3.w;            \
        if (gvalid) {                                                      \
            float4 _b0 = *(const float4*)(gp + (kc));                      \
            float4 _b1 = *(const float4*)(gp + (kc) + 4);                  \
            gv[0]=_b0.x; gv[1]=_b0.y; gv[2]=_b0.z; gv[3]=_b0.w;            \
            gv[4]=_b1.x; gv[5]=_b1.y; gv[6]=_b1.z; gv[7]=_b1.w;            \
        } else {                                                           \
            _Pragma("unroll") for (int _i = 0; _i < 8; _i++) gv[_i] = 0.0f;\
        }                                                                  \
    } while (0)

#define STORE_G1(pb)                                                       \
    do {                                                                   \
        _Pragma("unroll")                                                  \
        for (int _g = 0; _g < 2; _g++) {                                   \
            uint4 _uh, _um, _ul;                                           \
            split3_u4(xv + _g * 8, _uh, _um, _ul);                         \
            const int _o = toff(ar, akh + _g * 8);                         \
            *(uint4*)(sm + SA1(0, pb) + _o) = _uh;                         \
            *(uint4*)(sm + SA1(1, pb) + _o) = _um;                         \
            *(uint4*)(sm + SA1(2, pb) + _o) = _ul;                         \
        }                                                                  \
        {                                                                  \
            uint4 _uh, _um, _ul;                                           \
            split3_u4(gv, _uh, _um, _ul);                                  \
            _Pragma("unroll") for (int _i = 0; _i < 8; _i++) g2a += gv[_i] * gv[_i]; \
            const int _o = toff(br, bk8);                                  \
            *(uint4*)(sm + SB1(0, pb) + _o) = _uh;                         \
            *(uint4*)(sm + SB1(1, pb) + _o) = _um;                         \
            *(uint4*)(sm + SB1(2, pb) + _o) = _ul;                         \
        }                                                                  \
    } while (0)

    LOAD_G1(0);
    STORE_G1(0);
    __syncthreads();

    for (int c = 0; c < CH1; c++) {
        const int p = c & 1;
        const bool more = (c + 1 < CH1);
        if (more) LOAD_G1((c + 1) * KB);

#pragma unroll
        for (int as = 0; as < 3; as++) {
            const char* A = sm + SA1(as, p);
            uint32_t af[2][2][4];
#pragma unroll
            for (int mt = 0; mt < 2; mt++)
#pragma unroll
                for (int ks = 0; ks < 2; ks++) {
                    const int row = wm + mt * 16 + (lane >> 2);
                    const int kq = ks * 16 + (lane & 3) * 2;
                    af[mt][ks][0] = *(const uint32_t*)(A + toff(row, kq));
                    af[mt][ks][1] = *(const uint32_t*)(A + toff(row + 8, kq));
                    af[mt][ks][2] = *(const uint32_t*)(A + toff(row, kq + 8));
                    af[mt][ks][3] = *(const uint32_t*)(A + toff(row + 8, kq + 8));
                }
#pragma unroll
            for (int bs = 0; bs < 3; bs++) {
                if (as + bs >= 3) continue;
                const char* B = sm + SB1(bs, p);
#pragma unroll
                for (int ks = 0; ks < 2; ks++)
#pragma unroll
                    for (int nt = 0; nt < 4; nt++) {
                        const int col = wn + nt * 8 + (lane >> 2);
                        const int kq = ks * 16 + (lane & 3) * 2;
                        uint32_t bf[2];
                        bf[0] = *(const uint32_t*)(B + toff(col, kq));
                        bf[1] = *(const uint32_t*)(B + toff(col, kq + 8));
#pragma unroll
                        for (int mt = 0; mt < 2; mt++) mma16816(acc[mt][nt], af[mt][ks], bf);
                    }
            }
        }
        if (more) STORE_G1(p ^ 1);
        __syncthreads();
    }

    g2a += __shfl_xor_sync(0xffffffffu, g2a, 1);
    g2a += __shfl_xor_sync(0xffffffffu, g2a, 2);
    if ((tid & 3) == 0) g2s[br] = g2a;
    __syncthreads();

#pragma unroll
    for (int mt = 0; mt < 2; mt++) {
#pragma unroll
        for (int nt = 0; nt < 4; nt++) {
            const int lc = wn + nt * 8 + (lane & 3) * 2;
            const int n = nblk + lc;
            if (n >= NDIM) continue;
            const int row0 = wm + mt * 16 + (lane >> 2);
            const float a0 = alpha_s[row0], b0 = beta_s[row0];
            const float a1 = alpha_s[row0 + 8], b1 = beta_s[row0 + 8];
            const float q0 = g2s[lc], q1 = g2s[lc + 1];
            *(float2*)&g_s[(size_t)row0 * NDIM + n] =
                make_float2(a0 * acc[mt][nt][0] - b0 * q0, a0 * acc[mt][nt][1] - b0 * q1);
            *(float2*)&g_s[(size_t)(row0 + 8) * NDIM + n] =
                make_float2(a1 * acc[mt][nt][2] - b1 * q0, a1 * acc[mt][nt][3] - b1 * q1);
        }
    }
#undef LOAD_G1
#undef STORE_G1
}

// ---------------------------------------------------------------------------
// Softmax stats + unnormalized e = exp(s-m) pre-split to bf16 (h, l).
// ---------------------------------------------------------------------------
__global__ __launch_bounds__(256) void softmax_stats_kernel()
{
    const int b = blockIdx.x;
    const int tid = threadIdx.x;
    const float* row = g_s + (size_t)b * NDIM;
    __shared__ float red[256];

    float m = -INFINITY;
    for (int i = tid; i < NDIM; i += 256) m = fmaxf(m, row[i]);
    red[tid] = m;
    __syncthreads();
    for (int s = 128; s > 0; s >>= 1) {
        if (tid < s) red[tid] = fmaxf(red[tid], red[tid + s]);
        __syncthreads();
    }
    m = red[0];
    __syncthreads();

    float sum = 0.0f;
    for (int i = tid; i < NDIM; i += 256) {
        const float e = __expf(row[i] - m);
        sum += e;
        const float h = bfround(e);
        g_eh[(size_t)b * NDIM + i] = __float2bfloat16(h);
        g_el[(size_t)b * NDIM + i] = __float2bfloat16(e - h);
    }
    red[tid] = sum;
    __syncthreads();
    for (int s = 128; s > 0; s >>= 1) {
        if (tid < s) red[tid] += red[tid + s];
        __syncthreads();
    }
    if (tid == 0) g_rowsum[b] = red[0];
}

// ---------------------------------------------------------------------------
// GEMM2: partial[b,d] = sum_n e[b,n]*gt[n,d].  CTA tile 128b x 64d, k = n.
// E pre-split (copy); G transposed+split on the fly. 3 passes (2x2, as+bs<2).
// ---------------------------------------------------------------------------
__global__ __launch_bounds__(256, 2) void gemm2_kernel(const float* __restrict__ gt)
{
    extern __shared__ char sm[];
    const int tid = threadIdx.x, lane = tid & 31, warp = tid >> 5;
    const int wm = (warp & 3) * 32, wn = (warp >> 2) * 32;
    const int dblk = blockIdx.x * 64;
    const int nbase = blockIdx.y * SPAN2;

    // producer roles
    const int er = tid >> 1, ekh = (tid & 1) * 16;     // E: row er, 16 n
    const int gn2 = (tid & 15) * 2, gdg = (tid >> 4) * 4;  // G: 2 n-rows x 4 d

    float acc[2][4][4];
#pragma unroll
    for (int a = 0; a < 2; a++)
#pragma unroll
        for (int b = 0; b < 4; b++)
#pragma unroll
            for (int e = 0; e < 4; e++) acc[a][b][e] = 0.0f;

    uint4 evh[2], evl[2];
    float gva[4], gvb[4];

#define LOAD_G2(n0)                                                        \
    do {                                                                   \
        const size_t _eo = (size_t)er * NDIM + (n0) + ekh;                 \
        evh[0] = *(const uint4*)&g_eh[_eo];                                \
        evh[1] = *(const uint4*)&g_eh[_eo + 8];                            \
        evl[0] = *(const uint4*)&g_el[_eo];                                \
        evl[1] = *(const uint4*)&g_el[_eo + 8];                            \
        float4 _f = *(const float4*)(gt + (size_t)((n0) + gn2) * DDIM + dblk + gdg);     \
        gva[0]=_f.x; gva[1]=_f.y; gva[2]=_f.z; gva[3]=_f.w;                \
        _f = *(const float4*)(gt + (size_t)((n0) + gn2 + 1) * DDIM + dblk + gdg);        \
        gvb[0]=_f.x; gvb[1]=_f.y; gvb[2]=_f.z; gvb[3]=_f.w;                \
    } while (0)

#define STORE_G2(pb)                                                       \
    do {                                                                   \
        *(uint4*)(sm + SE2(0, pb) + toff(er, ekh)) = evh[0];               \
        *(uint4*)(sm + SE2(0, pb) + toff(er, ekh + 8)) = evh[1];           \
        *(uint4*)(sm + SE2(1, pb) + toff(er, ekh)) = evl[0];               \
        *(uint4*)(sm + SE2(1, pb) + toff(er, ekh + 8)) = evl[1];           \
        _Pragma("unroll")                                                  \
        for (int _j = 0; _j < 4; _j++) {                                   \
            const float _ha = bfround(gva[_j]);                            \
            const float _hb = bfround(gvb[_j]);                            \
            const int _o = toff(gdg + _j, gn2);                            \
            *(uint32_t*)(sm + SG2(0, pb) + _o) = pk2(_ha, _hb);            \
            *(uint32_t*)(sm + SG2(1, pb) + _o) = pk2(gva[_j] - _ha, gvb[_j] - _hb); \
        }                                                                  \
    } while (0)

    LOAD_G2(nbase);
    STORE_G2(0);
    __syncthreads();

    for (int c = 0; c < CH2; c++) {
        const int p = c & 1;
        const bool more = (c + 1 < CH2);
        if (more) LOAD_G2(nbase + (c + 1) * KB);

#pragma unroll
        for (int as = 0; as < 2; as++) {
            const char* A = sm + SE2(as, p);
            uint32_t af[2][2][4];
#pragma unroll
            for (int mt = 0; mt < 2; mt++)
#pragma unroll
                for (int ks = 0; ks < 2; ks++) {
                    const int row = wm + mt * 16 + (lane >> 2);
                    const int kq = ks * 16 + (lane & 3) * 2;
                    af[mt][ks][0] = *(const uint32_t*)(A + toff(row, kq));
                    af[mt][ks][1] = *(const uint32_t*)(A + toff(row + 8, kq));
                    af[mt][ks][2] = *(const uint32_t*)(A + toff(row, kq + 8));
                    af[mt][ks][3] = *(const uint32_t*)(A + toff(row + 8, kq + 8));
                }
#pragma unroll
            for (int bs = 0; bs < 2; bs++) {
                if (as + bs >= 2) continue;
                const char* B = sm + SG2(bs, p);
#pragma unroll
                for (int ks = 0; ks < 2; ks++)
#pragma unroll
                    for (int nt = 0; nt < 4; nt++) {
                        const int col = wn + nt * 8 + (lane >> 2);
                        const int kq = ks * 16 + (lane & 3) * 2;
                        uint32_t bf[2];
                        bf[0] = *(const uint32_t*)(B + toff(col, kq));
                        bf[1] = *(const uint32_t*)(B + toff(col, kq + 8));
#pragma unroll
                        for (int mt = 0; mt < 2; mt++) mma16816(acc[mt][nt], af[mt][ks], bf);
                    }
            }
        }
        if (more) STORE_G2(p ^ 1);
        __syncthreads();
    }

    float* outp = g_part + (size_t)blockIdx.y * BDIM * DDIM;
#pragma unroll
    for (int mt = 0; mt < 2; mt++)
#pragma unroll
        for (int nt = 0; nt < 4; nt++) {
            const int row0 = wm + mt * 16 + (lane >> 2);
            const int col = dblk + wn + nt * 8 + (lane & 3) * 2;
            *(float2*)&outp[(size_t)row0 * DDIM + col] = make_float2(acc[mt][nt][0], acc[mt][nt][1]);
            *(float2*)&outp[(size_t)(row0 + 8) * DDIM + col] = make_float2(acc[mt][nt][2], acc[mt][nt][3]);
        }
#undef LOAD_G2
#undef STORE_G2
}

// ---------------------------------------------------------------------------
// Epilogue: out = (sum_splits partial / rowsum - x) / sig
// ---------------------------------------------------------------------------
__global__ __launch_bounds__(256) void epilogue_kernel(const float* __restrict__ x,
                                                       const float* __restrict__ t,
                                                       float* __restrict__ out)
{
    const int idx = blockIdx.x * 256 + threadIdx.x;
    if (idx >= BDIM * DDIM) return;
    const int b = idx / DDIM;
    float a = 0.0f;
#pragma unroll
    for (int s = 0; s < NSPLIT; s++) a += g_part[(size_t)s * BDIM * DDIM + idx];
    const float tt = t[b] * (1.0f / 999.0f);
    const float sg = 1.0f - tt;
    out[idx] = (a / g_rowsum[b] - x[idx]) / sg;
}

extern "C" void kernel_launch(void* const* d_in, const int* in_sizes, int n_in,
                              void* d_out, int out_size)
{
    const float* xt = (const float*)d_in[0];
    const float* t  = (const float*)d_in[1];
    const float* gt = (const float*)d_in[2];
    float* out = (float*)d_out;

    static int attr_done = 0;
    if (!attr_done) {
        cudaFuncSetAttribute(gemm1_kernel, cudaFuncAttributeMaxDynamicSharedMemorySize, SM1_TOTAL);
        cudaFuncSetAttribute(gemm2_kernel, cudaFuncAttributeMaxDynamicSharedMemorySize, SM2_TOTAL);
        attr_done = 1;
    }

    gemm1_kernel<<<NT1, 256, SM1_TOTAL>>>(xt, t, gt);
    softmax_stats_kernel<<<BDIM, 256>>>();
    dim3 g2(DT2, NSPLIT);
    gemm2_kernel<<<g2, 256, SM2_TOTAL>>>(gt);
    epilogue_kernel<<<(BDIM * DDIM + 255) / 256, 256>>>(xt, t, out);
}

// round 8
// speedup vs baseline: 2.9377x; 1.3356x over previous
#include <cuda_runtime.h>
#include <cuda_bf16.h>
#include <math.h>
#include <stdint.h>

#define NDIM 20000
#define DDIM 3072
#define BDIM 128
#define KB 32
#define CH1 (DDIM / KB)            /* 96 */
#define NT1 ((NDIM + 63) / 64)     /* 313 */
#define NSPLIT 6
#define SPAN2 3360                 /* splits 0-4: 105 chunks; split 5: 3200 = 100 chunks */
#define DT2 (DDIM / 64)            /* 48 */

// GEMM1 smem: per buffer 2 A-splits (128x32 bf16 = 8KB) + 2 B-splits (64x32 = 4KB)
#define SA1(s, p) ((p) * 24576 + (s) * 8192)
#define SB1(s, p) ((p) * 24576 + 16384 + (s) * 4096)
#define SM1_TOTAL (2 * 24576)
// GEMM2 smem: per buffer 2 E-splits (8KB) + 2 G-splits (4KB)
#define SE2(s, p) ((p) * 24576 + (s) * 8192)
#define SG2(s, p) ((p) * 24576 + 16384 + (s) * 4096)
#define SM2_TOTAL (2 * 24576)

// Scratch (allocation-free rule: __device__ globals)
__device__ float g_s[BDIM * NDIM];
__device__ float g_rowsum[BDIM];
__device__ __nv_bfloat16 g_eh[BDIM * NDIM];
__device__ __nv_bfloat16 g_el[BDIM * NDIM];
__device__ float g_part[NSPLIT * BDIM * DDIM];

// Swizzled byte offset inside a [rows x 32k] bf16 tile (row stride 64B).
__device__ __forceinline__ int toff(int row, int k)
{
    return row * 64 + ((((k >> 3) & 3) ^ ((row >> 1) & 3)) << 4) + ((k * 2) & 15);
}

__device__ __forceinline__ float bfround(float v) { return __bfloat162float(__float2bfloat16(v)); }
__device__ __forceinline__ uint32_t pk2(float a, float b)
{
    __nv_bfloat162 t = __floats2bfloat162_rn(a, b);
    return *reinterpret_cast<uint32_t*>(&t);
}
__device__ __forceinline__ void split2_u4(const float v[8], uint4& uh, uint4& ul)
{
    float h[8], l[8];
#pragma unroll
    for (int i = 0; i < 8; i++) {
        h[i] = bfround(v[i]);
        l[i] = v[i] - h[i];
    }
    uh = make_uint4(pk2(h[0], h[1]), pk2(h[2], h[3]), pk2(h[4], h[5]), pk2(h[6], h[7]));
    ul = make_uint4(pk2(l[0], l[1]), pk2(l[2], l[3]), pk2(l[4], l[5]), pk2(l[6], l[7]));
}
__device__ __forceinline__ void mma16816(float c[4], const uint32_t a[4], const uint32_t b[2])
{
    asm volatile(
        "mma.sync.aligned.m16n8k16.row.col.f32.bf16.bf16.f32 "
        "{%0,%1,%2,%3}, {%4,%5,%6,%7}, {%8,%9}, {%0,%1,%2,%3};"
        : "+f"(c[0]), "+f"(c[1]), "+f"(c[2]), "+f"(c[3])
        : "r"(a[0]), "r"(a[1]), "r"(a[2]), "r"(a[3]), "r"(b[0]), "r"(b[1]));
}

// ---------------------------------------------------------------------------
// GEMM1: s[b,n] = alpha[b]*(x_b.gt_n) - beta[b]*||gt_n||^2
// CTA tile 128b x 64n, KB=32, double-buffered, 3 split passes (2x2, as+bs<2).
// ---------------------------------------------------------------------------
__global__ __launch_bounds__(256, 2) void gemm1_kernel(const float* __restrict__ x,
                                                       const float* __restrict__ t,
                                                       const float* __restrict__ gt)
{
    extern __shared__ char sm[];
    __shared__ float alpha_s[128], beta_s[128], g2s[64];

    const int tid = threadIdx.x, lane = tid & 31, warp = tid >> 5;
    const int wm = (warp & 3) * 32, wn = (warp >> 2) * 32;
    const int nblk = blockIdx.x * 64;

    if (tid < 128) {
        const float tt = t[tid] * (1.0f / 999.0f);
        const float sg = 1.0f - tt;
        const float inv = 1.0f / (sg * sg);
        alpha_s[tid] = tt * inv;
        beta_s[tid] = 0.5f * tt * tt * inv;
    }

    // producer roles
    const int ar = tid >> 1, akh = (tid & 1) * 16;     // x: row ar, k [akh, akh+16)
    const int br = tid >> 2, bk8 = (tid & 3) * 8;      // gt: row br, k [bk8, bk8+8)
    const int gn = nblk + br;
    const bool gvalid = (gn < NDIM);
    const float* xp = x + (size_t)ar * DDIM + akh;
    const float* gp = gt + (size_t)gn * DDIM + bk8;

    float acc[2][4][4];
#pragma unroll
    for (int a = 0; a < 2; a++)
#pragma unroll
        for (int b = 0; b < 4; b++)
#pragma unroll
            for (int e = 0; e < 4; e++) acc[a][b][e] = 0.0f;
    float g2a = 0.0f;
    float xv[16], gv[8];

#define LOAD_G1(kc)                                                        \
    do {                                                                   \
        float4 _a0 = *(const float4*)(xp + (kc));                          \
        float4 _a1 = *(const float4*)(xp + (kc) + 4);                      \
        float4 _a2 = *(const float4*)(xp + (kc) + 8);                      \
        float4 _a3 = *(const float4*)(xp + (kc) + 12);                     \
        xv[0]=_a0.x; xv[1]=_a0.y; xv[2]=_a0.z; xv[3]=_a0.w;                \
        xv[4]=_a1.x; xv[5]=_a1.y; xv[6]=_a1.z; xv[7]=_a1.w;                \
        xv[8]=_a2.x; xv[9]=_a2.y; xv[10]=_a2.z; xv[11]=_a2.w;              \
        xv[12]=_a3.x; xv[13]=_a3.y; xv[14]=_a3.z; xv[15]=_a3.w;            \
        if (gvalid) {                                                      \
            float4 _b0 = *(const float4*)(gp + (kc));                      \
            float4 _b1 = *(const float4*)(gp + (kc) + 4);                  \
            gv[0]=_b0.x; gv[1]=_b0.y; gv[2]=_b0.z; gv[3]=_b0.w;            \
            gv[4]=_b1.x; gv[5]=_b1.y; gv[6]=_b1.z; gv[7]=_b1.w;            \
        } else {                                                           \
            _Pragma("unroll") for (int _i = 0; _i < 8; _i++) gv[_i] = 0.0f;\
        }                                                                  \
    } while (0)

#define STORE_G1(pb)                                                       \
    do {                                                                   \
        _Pragma("unroll")                                                  \
        for (int _g = 0; _g < 2; _g++) {                                   \
            uint4 _uh, _ul;                                                \
            split2_u4(xv + _g * 8, _uh, _ul);                              \
            const int _o = toff(ar, akh + _g * 8);                         \
            *(uint4*)(sm + SA1(0, pb) + _o) = _uh;                         \
            *(uint4*)(sm + SA1(1, pb) + _o) = _ul;                         \
        }                                                                  \
        {                                                                  \
            uint4 _uh, _ul;                                                \
            split2_u4(gv, _uh, _ul);                                       \
            _Pragma("unroll") for (int _i = 0; _i < 8; _i++) g2a += gv[_i] * gv[_i]; \
            const int _o = toff(br, bk8);                                  \
            *(uint4*)(sm + SB1(0, pb) + _o) = _uh;                         \
            *(uint4*)(sm + SB1(1, pb) + _o) = _ul;                         \
        }                                                                  \
    } while (0)

    LOAD_G1(0);
    STORE_G1(0);
    __syncthreads();

    for (int c = 0; c < CH1; c++) {
        const int p = c & 1;
        const bool more = (c + 1 < CH1);
        if (more) LOAD_G1((c + 1) * KB);

#pragma unroll
        for (int as = 0; as < 2; as++) {
            const char* A = sm + SA1(as, p);
            uint32_t af[2][2][4];
#pragma unroll
            for (int mt = 0; mt < 2; mt++)
#pragma unroll
                for (int ks = 0; ks < 2; ks++) {
                    const int row = wm + mt * 16 + (lane >> 2);
                    const int kq = ks * 16 + (lane & 3) * 2;
                    af[mt][ks][0] = *(const uint32_t*)(A + toff(row, kq));
                    af[mt][ks][1] = *(const uint32_t*)(A + toff(row + 8, kq));
                    af[mt][ks][2] = *(const uint32_t*)(A + toff(row, kq + 8));
                    af[mt][ks][3] = *(const uint32_t*)(A + toff(row + 8, kq + 8));
                }
#pragma unroll
            for (int bs = 0; bs < 2; bs++) {
                if (as + bs >= 2) continue;   // passes: hh, hl, lh
                const char* B = sm + SB1(bs, p);
#pragma unroll
                for (int ks = 0; ks < 2; ks++)
#pragma unroll
                    for (int nt = 0; nt < 4; nt++) {
                        const int col = wn + nt * 8 + (lane >> 2);
                        const int kq = ks * 16 + (lane & 3) * 2;
                        uint32_t bf[2];
                        bf[0] = *(const uint32_t*)(B + toff(col, kq));
                        bf[1] = *(const uint32_t*)(B + toff(col, kq + 8));
#pragma unroll
                        for (int mt = 0; mt < 2; mt++) mma16816(acc[mt][nt], af[mt][ks], bf);
                    }
            }
        }
        if (more) STORE_G1(p ^ 1);
        __syncthreads();
    }

    g2a += __shfl_xor_sync(0xffffffffu, g2a, 1);
    g2a += __shfl_xor_sync(0xffffffffu, g2a, 2);
    if ((tid & 3) == 0) g2s[br] = g2a;
    __syncthreads();

#pragma unroll
    for (int mt = 0; mt < 2; mt++) {
#pragma unroll
        for (int nt = 0; nt < 4; nt++) {
            const int lc = wn + nt * 8 + (lane & 3) * 2;
            const int n = nblk + lc;
            if (n >= NDIM) continue;
            const int row0 = wm + mt * 16 + (lane >> 2);
            const float a0 = alpha_s[row0], b0 = beta_s[row0];
            const float a1 = alpha_s[row0 + 8], b1 = beta_s[row0 + 8];
            const float q0 = g2s[lc], q1 = g2s[lc + 1];
            *(float2*)&g_s[(size_t)row0 * NDIM + n] =
                make_float2(a0 * acc[mt][nt][0] - b0 * q0, a0 * acc[mt][nt][1] - b0 * q1);
            *(float2*)&g_s[(size_t)(row0 + 8) * NDIM + n] =
                make_float2(a1 * acc[mt][nt][2] - b1 * q0, a1 * acc[mt][nt][3] - b1 * q1);
        }
    }
#undef LOAD_G1
#undef STORE_G1
}

// ---------------------------------------------------------------------------
// Softmax stats + unnormalized e = exp(s-m) pre-split to bf16 (h, l).
// ---------------------------------------------------------------------------
__global__ __launch_bounds__(256) void softmax_stats_kernel()
{
    const int b = blockIdx.x;
    const int tid = threadIdx.x;
    const float* row = g_s + (size_t)b * NDIM;
    __shared__ float red[256];

    float m = -INFINITY;
    for (int i = tid; i < NDIM; i += 256) m = fmaxf(m, row[i]);
    red[tid] = m;
    __syncthreads();
    for (int s = 128; s > 0; s >>= 1) {
        if (tid < s) red[tid] = fmaxf(red[tid], red[tid + s]);
        __syncthreads();
    }
    m = red[0];
    __syncthreads();

    float sum = 0.0f;
    for (int i = tid; i < NDIM; i += 256) {
        const float e = __expf(row[i] - m);
        sum += e;
        const float h = bfround(e);
        g_eh[(size_t)b * NDIM + i] = __float2bfloat16(h);
        g_el[(size_t)b * NDIM + i] = __float2bfloat16(e - h);
    }
    red[tid] = sum;
    __syncthreads();
    for (int s = 128; s > 0; s >>= 1) {
        if (tid < s) red[tid] += red[tid + s];
        __syncthreads();
    }
    if (tid == 0) g_rowsum[b] = red[0];
}

// ---------------------------------------------------------------------------
// GEMM2: partial[b,d] = sum_n e[b,n]*gt[n,d].  CTA tile 128b x 64d, k = n.
// E pre-split (copy); G transposed+split on the fly. 3 passes (2x2, as+bs<2).
// Grid 48 x 6 = 288 CTAs (balanced vs 296 slots).
// ---------------------------------------------------------------------------
__global__ __launch_bounds__(256, 2) void gemm2_kernel(const float* __restrict__ gt)
{
    extern __shared__ char sm[];
    const int tid = threadIdx.x, lane = tid & 31, warp = tid >> 5;
    const int wm = (warp & 3) * 32, wn = (warp >> 2) * 32;
    const int dblk = blockIdx.x * 64;
    const int nbase = blockIdx.y * SPAN2;
    const int ch = (blockIdx.y == NSPLIT - 1) ? ((NDIM - (NSPLIT - 1) * SPAN2) / KB) : (SPAN2 / KB);

    // producer roles
    const int er = tid >> 1, ekh = (tid & 1) * 16;     // E: row er, 16 n
    const int gn2 = (tid & 15) * 2, gdg = (tid >> 4) * 4;  // G: 2 n-rows x 4 d

    float acc[2][4][4];
#pragma unroll
    for (int a = 0; a < 2; a++)
#pragma unroll
        for (int b = 0; b < 4; b++)
#pragma unroll
            for (int e = 0; e < 4; e++) acc[a][b][e] = 0.0f;

    uint4 evh[2], evl[2];
    float gva[4], gvb[4];

#define LOAD_G2(n0)                                                        \
    do {                                                                   \
        const size_t _eo = (size_t)er * NDIM + (n0) + ekh;                 \
        evh[0] = *(const uint4*)&g_eh[_eo];                                \
        evh[1] = *(const uint4*)&g_eh[_eo + 8];                            \
        evl[0] = *(const uint4*)&g_el[_eo];                                \
        evl[1] = *(const uint4*)&g_el[_eo + 8];                            \
        float4 _f = *(const float4*)(gt + (size_t)((n0) + gn2) * DDIM + dblk + gdg);     \
        gva[0]=_f.x; gva[1]=_f.y; gva[2]=_f.z; gva[3]=_f.w;                \
        _f = *(const float4*)(gt + (size_t)((n0) + gn2 + 1) * DDIM + dblk + gdg);        \
        gvb[0]=_f.x; gvb[1]=_f.y; gvb[2]=_f.z; gvb[3]=_f.w;                \
    } while (0)

#define STORE_G2(pb)                                                       \
    do {                                                                   \
        *(uint4*)(sm + SE2(0, pb) + toff(er, ekh)) = evh[0];               \
        *(uint4*)(sm + SE2(0, pb) + toff(er, ekh + 8)) = evh[1];           \
        *(uint4*)(sm + SE2(1, pb) + toff(er, ekh)) = evl[0];               \
        *(uint4*)(sm + SE2(1, pb) + toff(er, ekh + 8)) = evl[1];           \
        _Pragma("unroll")                                                  \
        for (int _j = 0; _j < 4; _j++) {                                   \
            const float _ha = bfround(gva[_j]);                            \
            const float _hb = bfround(gvb[_j]);                            \
            const int _o = toff(gdg + _j, gn2);                            \
            *(uint32_t*)(sm + SG2(0, pb) + _o) = pk2(_ha, _hb);            \
            *(uint32_t*)(sm + SG2(1, pb) + _o) = pk2(gva[_j] - _ha, gvb[_j] - _hb); \
        }                                                                  \
    } while (0)

    LOAD_G2(nbase);
    STORE_G2(0);
    __syncthreads();

    for (int c = 0; c < ch; c++) {
        const int p = c & 1;
        const bool more = (c + 1 < ch);
        if (more) LOAD_G2(nbase + (c + 1) * KB);

#pragma unroll
        for (int as = 0; as < 2; as++) {
            const char* A = sm + SE2(as, p);
            uint32_t af[2][2][4];
#pragma unroll
            for (int mt = 0; mt < 2; mt++)
#pragma unroll
                for (int ks = 0; ks < 2; ks++) {
                    const int row = wm + mt * 16 + (lane >> 2);
                    const int kq = ks * 16 + (lane & 3) * 2;
                    af[mt][ks][0] = *(const uint32_t*)(A + toff(row, kq));
                    af[mt][ks][1] = *(const uint32_t*)(A + toff(row + 8, kq));
                    af[mt][ks][2] = *(const uint32_t*)(A + toff(row, kq + 8));
                    af[mt][ks][3] = *(const uint32_t*)(A + toff(row + 8, kq + 8));
                }
#pragma unroll
            for (int bs = 0; bs < 2; bs++) {
                if (as + bs >= 2) continue;
                const char* B = sm + SG2(bs, p);
#pragma unroll
                for (int ks = 0; ks < 2; ks++)
#pragma unroll
                    for (int nt = 0; nt < 4; nt++) {
                        const int col = wn + nt * 8 + (lane >> 2);
                        const int kq = ks * 16 + (lane & 3) * 2;
                        uint32_t bf[2];
                        bf[0] = *(const uint32_t*)(B + toff(col, kq));
                        bf[1] = *(const uint32_t*)(B + toff(col, kq + 8));
#pragma unroll
                        for (int mt = 0; mt < 2; mt++) mma16816(acc[mt][nt], af[mt][ks], bf);
                    }
            }
        }
        if (more) STORE_G2(p ^ 1);
        __syncthreads();
    }

    float* outp = g_part + (size_t)blockIdx.y * BDIM * DDIM;
#pragma unroll
    for (int mt = 0; mt < 2; mt++)
#pragma unroll
        for (int nt = 0; nt < 4; nt++) {
            const int row0 = wm + mt * 16 + (lane >> 2);
            const int col = dblk + wn + nt * 8 + (lane & 3) * 2;
            *(float2*)&outp[(size_t)row0 * DDIM + col] = make_float2(acc[mt][nt][0], acc[mt][nt][1]);
            *(float2*)&outp[(size_t)(row0 + 8) * DDIM + col] = make_float2(acc[mt][nt][2], acc[mt][nt][3]);
        }
#undef LOAD_G2
#undef STORE_G2
}

// ---------------------------------------------------------------------------
// Epilogue: out = (sum_splits partial / rowsum - x) / sig
// ---------------------------------------------------------------------------
__global__ __launch_bounds__(256) void epilogue_kernel(const float* __restrict__ x,
                                                       const float* __restrict__ t,
                                                       float* __restrict__ out)
{
    const int idx = blockIdx.x * 256 + threadIdx.x;
    if (idx >= BDIM * DDIM) return;
    const int b = idx / DDIM;
    float a = 0.0f;
#pragma unroll
    for (int s = 0; s < NSPLIT; s++) a += g_part[(size_t)s * BDIM * DDIM + idx];
    const float tt = t[b] * (1.0f / 999.0f);
    const float sg = 1.0f - tt;
    out[idx] = (a / g_rowsum[b] - x[idx]) / sg;
}

extern "C" void kernel_launch(void* const* d_in, const int* in_sizes, int n_in,
                              void* d_out, int out_size)
{
    const float* xt = (const float*)d_in[0];
    const float* t  = (const float*)d_in[1];
    const float* gt = (const float*)d_in[2];
    float* out = (float*)d_out;

    static int attr_done = 0;
    if (!attr_done) {
        cudaFuncSetAttribute(gemm1_kernel, cudaFuncAttributeMaxDynamicSharedMemorySize, SM1_TOTAL);
        cudaFuncSetAttribute(gemm2_kernel, cudaFuncAttributeMaxDynamicSharedMemorySize, SM2_TOTAL);
        attr_done = 1;
    }

    gemm1_kernel<<<NT1, 256, SM1_TOTAL>>>(xt, t, gt);
    softmax_stats_kernel<<<BDIM, 256>>>();
    dim3 g2(DT2, NSPLIT);
    gemm2_kernel<<<g2, 256, SM2_TOTAL>>>(gt);
    epilogue_kernel<<<(BDIM * DDIM + 255) / 256, 256>>>(xt, t, out);
}

// round 9
// speedup vs baseline: 2.9442x; 1.0022x over previous
#include <cuda_runtime.h>
#include <cuda_bf16.h>
#include <math.h>
#include <stdint.h>

#define NDIM 20000
#define DDIM 3072
#define BDIM 128
#define KB 32
#define KSPLIT 4
#define KSPAN (DDIM / KSPLIT)      /* 768 */
#define CH1 (KSPAN / KB)           /* 24 */
#define NT1 ((NDIM + 63) / 64)     /* 313 */
#define NSPLIT 6
#define SPAN2 3360                 /* splits 0-4: 105 chunks; split 5: 3200 = 100 chunks */
#define DT2 (DDIM / 64)            /* 48 */

// GEMM1 smem: per buffer 2 A-splits (128x32 bf16 = 8KB) + 2 B-splits (64x32 = 4KB)
#define SA1(s, p) ((p) * 24576 + (s) * 8192)
#define SB1(s, p) ((p) * 24576 + 16384 + (s) * 4096)
#define SM1_TOTAL (2 * 24576)
// GEMM2 smem layout identical
#define SE2(s, p) ((p) * 24576 + (s) * 8192)
#define SG2(s, p) ((p) * 24576 + 16384 + (s) * 4096)
#define SM2_TOTAL (2 * 24576)

// Scratch (allocation-free rule: __device__ globals)
__device__ float g_dotp[KSPLIT * BDIM * NDIM];   // raw dot partials, 41 MB
__device__ float g_g2p[KSPLIT * NDIM];           // ||gt||^2 partials
__device__ float g_s[BDIM * NDIM];               // logits
__device__ float g_rowsum[BDIM];
__device__ __nv_bfloat16 g_eh[BDIM * NDIM];
__device__ __nv_bfloat16 g_el[BDIM * NDIM];
__device__ float g_part[NSPLIT * BDIM * DDIM];

// Swizzled byte offset inside a [rows x 32k] bf16 tile (row stride 64B).
__device__ __forceinline__ int toff(int row, int k)
{
    return row * 64 + ((((k >> 3) & 3) ^ ((row >> 1) & 3)) << 4) + ((k * 2) & 15);
}

__device__ __forceinline__ float bfround(float v) { return __bfloat162float(__float2bfloat16(v)); }
__device__ __forceinline__ uint32_t pk2(float a, float b)
{
    __nv_bfloat162 t = __floats2bfloat162_rn(a, b);
    return *reinterpret_cast<uint32_t*>(&t);
}
__device__ __forceinline__ void split2_u4(const float v[8], uint4& uh, uint4& ul)
{
    float h[8], l[8];
#pragma unroll
    for (int i = 0; i < 8; i++) {
        h[i] = bfround(v[i]);
        l[i] = v[i] - h[i];
    }
    uh = make_uint4(pk2(h[0], h[1]), pk2(h[2], h[3]), pk2(h[4], h[5]), pk2(h[6], h[7]));
    ul = make_uint4(pk2(l[0], l[1]), pk2(l[2], l[3]), pk2(l[4], l[5]), pk2(l[6], l[7]));
}
__device__ __forceinline__ void mma16816(float c[4], const uint32_t a[4], const uint32_t b[2])
{
    asm volatile(
        "mma.sync.aligned.m16n8k16.row.col.f32.bf16.bf16.f32 "
        "{%0,%1,%2,%3}, {%4,%5,%6,%7}, {%8,%9}, {%0,%1,%2,%3};"
        : "+f"(c[0]), "+f"(c[1]), "+f"(c[2]), "+f"(c[3])
        : "r"(a[0]), "r"(a[1]), "r"(a[2]), "r"(a[3]), "r"(b[0]), "r"(b[1]));
}

// ---------------------------------------------------------------------------
// GEMM1 (split-K over D): dotp[kz][b][n] = sum_{k in range} x[b,k]*gt[n,k]
// CTA tile 128b x 64n x 768k. 3 split passes (2x2, as+bs<2). Grid 313 x 4.
// ---------------------------------------------------------------------------
__global__ __launch_bounds__(256, 2) void gemm1_kernel(const float* __restrict__ x,
                                                       const float* __restrict__ gt)
{
    extern __shared__ char sm[];

    const int tid = threadIdx.x, lane = tid & 31, warp = tid >> 5;
    const int wm = (warp & 3) * 32, wn = (warp >> 2) * 32;
    const int nblk = blockIdx.x * 64;
    const int kz = blockIdx.y;
    const int kbase = kz * KSPAN;

    // producer roles
    const int ar = tid >> 1, akh = (tid & 1) * 16;     // x: row ar, k [akh, akh+16)
    const int br = tid >> 2, bk8 = (tid & 3) * 8;      // gt: row br, k [bk8, bk8+8)
    const int gn = nblk + br;
    const bool gvalid = (gn < NDIM);
    const float* xp = x + (size_t)ar * DDIM + kbase + akh;
    const float* gp = gt + (size_t)gn * DDIM + kbase + bk8;

    float acc[2][4][4];
#pragma unroll
    for (int a = 0; a < 2; a++)
#pragma unroll
        for (int b = 0; b < 4; b++)
#pragma unroll
            for (int e = 0; e < 4; e++) acc[a][b][e] = 0.0f;
    float g2a = 0.0f;
    float xv[16], gv[8];

#define LOAD_G1(kc)                                                        \
    do {                                                                   \
        float4 _a0 = *(const float4*)(xp + (kc));                          \
        float4 _a1 = *(const float4*)(xp + (kc) + 4);                      \
        float4 _a2 = *(const float4*)(xp + (kc) + 8);                      \
        float4 _a3 = *(const float4*)(xp + (kc) + 12);                     \
        xv[0]=_a0.x; xv[1]=_a0.y; xv[2]=_a0.z; xv[3]=_a0.w;                \
        xv[4]=_a1.x; xv[5]=_a1.y; xv[6]=_a1.z; xv[7]=_a1.w;                \
        xv[8]=_a2.x; xv[9]=_a2.y; xv[10]=_a2.z; xv[11]=_a2.w;              \
        xv[12]=_a3.x; xv[13]=_a3.y; xv[14]=_a3.z; xv[15]=_a3.w;            \
        if (gvalid) {                                                      \
            float4 _b0 = *(const float4*)(gp + (kc));                      \
            float4 _b1 = *(const float4*)(gp + (kc) + 4);                  \
            gv[0]=_b0.x; gv[1]=_b0.y; gv[2]=_b0.z; gv[3]=_b0.w;            \
            gv[4]=_b1.x; gv[5]=_b1.y; gv[6]=_b1.z; gv[7]=_b1.w;            \
        } else {                                                           \
            _Pragma("unroll") for (int _i = 0; _i < 8; _i++) gv[_i] = 0.0f;\
        }                                                                  \
    } while (0)

#define STORE_G1(pb)                                                       \
    do {                                                                   \
        _Pragma("unroll")                                                  \
        for (int _g = 0; _g < 2; _g++) {                                   \
            uint4 _uh, _ul;                                                \
            split2_u4(xv + _g * 8, _uh, _ul);                              \
            const int _o = toff(ar, akh + _g * 8);                         \
            *(uint4*)(sm + SA1(0, pb) + _o) = _uh;                         \
            *(uint4*)(sm + SA1(1, pb) + _o) = _ul;                         \
        }                                                                  \
        {                                                                  \
            uint4 _uh, _ul;                                                \
            split2_u4(gv, _uh, _ul);                                       \
            _Pragma("unroll") for (int _i = 0; _i < 8; _i++) g2a += gv[_i] * gv[_i]; \
            const int _o = toff(br, bk8);                                  \
            *(uint4*)(sm + SB1(0, pb) + _o) = _uh;                         \
            *(uint4*)(sm + SB1(1, pb) + _o) = _ul;                         \
        }                                                                  \
    } while (0)

    LOAD_G1(0);
    STORE_G1(0);
    __syncthreads();

    for (int c = 0; c < CH1; c++) {
        const int p = c & 1;
        const bool more = (c + 1 < CH1);
        if (more) LOAD_G1((c + 1) * KB);

#pragma unroll
        for (int as = 0; as < 2; as++) {
            const char* A = sm + SA1(as, p);
            uint32_t af[2][2][4];
#pragma unroll
            for (int mt = 0; mt < 2; mt++)
#pragma unroll
                for (int ks = 0; ks < 2; ks++) {
                    const int row = wm + mt * 16 + (lane >> 2);
                    const int kq = ks * 16 + (lane & 3) * 2;
                    af[mt][ks][0] = *(const uint32_t*)(A + toff(row, kq));
                    af[mt][ks][1] = *(const uint32_t*)(A + toff(row + 8, kq));
                    af[mt][ks][2] = *(const uint32_t*)(A + toff(row, kq + 8));
                    af[mt][ks][3] = *(const uint32_t*)(A + toff(row + 8, kq + 8));
                }
#pragma unroll
            for (int bs = 0; bs < 2; bs++) {
                if (as + bs >= 2) continue;   // passes: hh, hl, lh
                const char* B = sm + SB1(bs, p);
#pragma unroll
                for (int ks = 0; ks < 2; ks++)
#pragma unroll
                    for (int nt = 0; nt < 4; nt++) {
                        const int col = wn + nt * 8 + (lane >> 2);
                        const int kq = ks * 16 + (lane & 3) * 2;
                        uint32_t bf[2];
                        bf[0] = *(const uint32_t*)(B + toff(col, kq));
                        bf[1] = *(const uint32_t*)(B + toff(col, kq + 8));
#pragma unroll
                        for (int mt = 0; mt < 2; mt++) mma16816(acc[mt][nt], af[mt][ks], bf);
                    }
            }
        }
        if (more) STORE_G1(p ^ 1);
        __syncthreads();
    }

    g2a += __shfl_xor_sync(0xffffffffu, g2a, 1);
    g2a += __shfl_xor_sync(0xffffffffu, g2a, 2);
    if ((tid & 3) == 0 && gvalid) g_g2p[(size_t)kz * NDIM + gn] = g2a;

    float* dbase = g_dotp + (size_t)kz * BDIM * NDIM;
#pragma unroll
    for (int mt = 0; mt < 2; mt++) {
#pragma unroll
        for (int nt = 0; nt < 4; nt++) {
            const int lc = wn + nt * 8 + (lane & 3) * 2;
            const int n = nblk + lc;
            if (n >= NDIM) continue;
            const int row0 = wm + mt * 16 + (lane >> 2);
            *(float2*)&dbase[(size_t)row0 * NDIM + n] = make_float2(acc[mt][nt][0], acc[mt][nt][1]);
            *(float2*)&dbase[(size_t)(row0 + 8) * NDIM + n] = make_float2(acc[mt][nt][2], acc[mt][nt][3]);
        }
    }
#undef LOAD_G1
#undef STORE_G1
}

// ---------------------------------------------------------------------------
// Combine + softmax stats: s = alpha*sum(dotp) - beta*sum(g2p); rowmax;
// unnormalized e = exp(s-m) pre-split to bf16 (h, l); rowsum.
// ---------------------------------------------------------------------------
__global__ __launch_bounds__(256) void softmax_stats_kernel(const float* __restrict__ t)
{
    const int b = blockIdx.x;
    const int tid = threadIdx.x;
    __shared__ float red[256];

    const float tt = t[b] * (1.0f / 999.0f);
    const float sg = 1.0f - tt;
    const float inv = 1.0f / (sg * sg);
    const float alpha = tt * inv;
    const float beta = 0.5f * tt * tt * inv;

    const float* d0 = g_dotp + (size_t)b * NDIM;
    const float* d1 = d0 + (size_t)BDIM * NDIM;
    const float* d2 = d1 + (size_t)BDIM * NDIM;
    const float* d3 = d2 + (size_t)BDIM * NDIM;

    float m = -INFINITY;
    for (int i = tid; i < NDIM; i += 256) {
        const float dot = (d0[i] + d1[i]) + (d2[i] + d3[i]);
        const float g2 = (g_g2p[i] + g_g2p[NDIM + i]) + (g_g2p[2 * NDIM + i] + g_g2p[3 * NDIM + i]);
        const float s = alpha * dot - beta * g2;
        g_s[(size_t)b * NDIM + i] = s;
        m = fmaxf(m, s);
    }
    red[tid] = m;
    __syncthreads();
    for (int s = 128; s > 0; s >>= 1) {
        if (tid < s) red[tid] = fmaxf(red[tid], red[tid + s]);
        __syncthreads();
    }
    m = red[0];
    __syncthreads();

    float sum = 0.0f;
    for (int i = tid; i < NDIM; i += 256) {
        const float e = __expf(g_s[(size_t)b * NDIM + i] - m);
        sum += e;
        const float h = bfround(e);
        g_eh[(size_t)b * NDIM + i] = __float2bfloat16(h);
        g_el[(size_t)b * NDIM + i] = __float2bfloat16(e - h);
    }
    red[tid] = sum;
    __syncthreads();
    for (int s = 128; s > 0; s >>= 1) {
        if (tid < s) red[tid] += red[tid + s];
        __syncthreads();
    }
    if (tid == 0) g_rowsum[b] = red[0];
}

// ---------------------------------------------------------------------------
// GEMM2: partial[b,d] = sum_n e[b,n]*gt[n,d].  CTA tile 128b x 64d, k = n.
// E pre-split (copy); G transposed+split on the fly. 3 passes (2x2, as+bs<2).
// Grid 48 x 6 = 288 CTAs.
// ---------------------------------------------------------------------------
__global__ __launch_bounds__(256, 2) void gemm2_kernel(const float* __restrict__ gt)
{
    extern __shared__ char sm[];
    const int tid = threadIdx.x, lane = tid & 31, warp = tid >> 5;
    const int wm = (warp & 3) * 32, wn = (warp >> 2) * 32;
    const int dblk = blockIdx.x * 64;
    const int nbase = blockIdx.y * SPAN2;
    const int ch = (blockIdx.y == NSPLIT - 1) ? ((NDIM - (NSPLIT - 1) * SPAN2) / KB) : (SPAN2 / KB);

    // producer roles
    const int er = tid >> 1, ekh = (tid & 1) * 16;     // E: row er, 16 n
    const int gn2 = (tid & 15) * 2, gdg = (tid >> 4) * 4;  // G: 2 n-rows x 4 d

    float acc[2][4][4];
#pragma unroll
    for (int a = 0; a < 2; a++)
#pragma unroll
        for (int b = 0; b < 4; b++)
#pragma unroll
            for (int e = 0; e < 4; e++) acc[a][b][e] = 0.0f;

    uint4 evh[2], evl[2];
    float gva[4], gvb[4];

#define LOAD_G2(n0)                                                        \
    do {                                                                   \
        const size_t _eo = (size_t)er * NDIM + (n0) + ekh;                 \
        evh[0] = *(const uint4*)&g_eh[_eo];                                \
        evh[1] = *(const uint4*)&g_eh[_eo + 8];                            \
        evl[0] = *(const uint4*)&g_el[_eo];                                \
        evl[1] = *(const uint4*)&g_el[_eo + 8];                            \
        float4 _f = *(const float4*)(gt + (size_t)((n0) + gn2) * DDIM + dblk + gdg);     \
        gva[0]=_f.x; gva[1]=_f.y; gva[2]=_f.z; gva[3]=_f.w;                \
        _f = *(const float4*)(gt + (size_t)((n0) + gn2 + 1) * DDIM + dblk + gdg);        \
        gvb[0]=_f.x; gvb[1]=_f.y; gvb[2]=_f.z; gvb[3]=_f.w;                \
    } while (0)

#define STORE_G2(pb)                                                       \
    do {                                                                   \
        *(uint4*)(sm + SE2(0, pb) + toff(er, ekh)) = evh[0];               \
        *(uint4*)(sm + SE2(0, pb) + toff(er, ekh + 8)) = evh[1];           \
        *(uint4*)(sm + SE2(1, pb) + toff(er, ekh)) = evl[0];               \
        *(uint4*)(sm + SE2(1, pb) + toff(er, ekh + 8)) = evl[1];           \
        _Pragma("unroll")                                                  \
        for (int _j = 0; _j < 4; _j++) {                                   \
            const float _ha = bfround(gva[_j]);                            \
            const float _hb = bfround(gvb[_j]);                            \
            const int _o = toff(gdg + _j, gn2);                            \
            *(uint32_t*)(sm + SG2(0, pb) + _o) = pk2(_ha, _hb);            \
            *(uint32_t*)(sm + SG2(1, pb) + _o) = pk2(gva[_j] - _ha, gvb[_j] - _hb); \
        }                                                                  \
    } while (0)

    LOAD_G2(nbase);
    STORE_G2(0);
    __syncthreads();

    for (int c = 0; c < ch; c++) {
        const int p = c & 1;
        const bool more = (c + 1 < ch);
        if (more) LOAD_G2(nbase + (c + 1) * KB);

#pragma unroll
        for (int as = 0; as < 2; as++) {
            const char* A = sm + SE2(as, p);
            uint32_t af[2][2][4];
#pragma unroll
            for (int mt = 0; mt < 2; mt++)
#pragma unroll
                for (int ks = 0; ks < 2; ks++) {
                    const int row = wm + mt * 16 + (lane >> 2);
                    const int kq = ks * 16 + (lane & 3) * 2;
                    af[mt][ks][0] = *(const uint32_t*)(A + toff(row, kq));
                    af[mt][ks][1] = *(const uint32_t*)(A + toff(row + 8, kq));
                    af[mt][ks][2] = *(const uint32_t*)(A + toff(row, kq + 8));
                    af[mt][ks][3] = *(const uint32_t*)(A + toff(row + 8, kq + 8));
                }
#pragma unroll
            for (int bs = 0; bs < 2; bs++) {
                if (as + bs >= 2) continue;
                const char* B = sm + SG2(bs, p);
#pragma unroll
                for (int ks = 0; ks < 2; ks++)
#pragma unroll
                    for (int nt = 0; nt < 4; nt++) {
                        const int col = wn + nt * 8 + (lane >> 2);
                        const int kq = ks * 16 + (lane & 3) * 2;
                        uint32_t bf[2];
                        bf[0] = *(const uint32_t*)(B + toff(col, kq));
                        bf[1] = *(const uint32_t*)(B + toff(col, kq + 8));
#pragma unroll
                        for (int mt = 0; mt < 2; mt++) mma16816(acc[mt][nt], af[mt][ks], bf);
                    }
            }
        }
        if (more) STORE_G2(p ^ 1);
        __syncthreads();
    }

    float* outp = g_part + (size_t)blockIdx.y * BDIM * DDIM;
#pragma unroll
    for (int mt = 0; mt < 2; mt++)
#pragma unroll
        for (int nt = 0; nt < 4; nt++) {
            const int row0 = wm + mt * 16 + (lane >> 2);
            const int col = dblk + wn + nt * 8 + (lane & 3) * 2;
            *(float2*)&outp[(size_t)row0 * DDIM + col] = make_float2(acc[mt][nt][0], acc[mt][nt][1]);
            *(float2*)&outp[(size_t)(row0 + 8) * DDIM + col] = make_float2(acc[mt][nt][2], acc[mt][nt][3]);
        }
#undef LOAD_G2
#undef STORE_G2
}

// ---------------------------------------------------------------------------
// Epilogue: out = (sum_splits partial / rowsum - x) / sig
// ---------------------------------------------------------------------------
__global__ __launch_bounds__(256) void epilogue_kernel(const float* __restrict__ x,
                                                       const float* __restrict__ t,
                                                       float* __restrict__ out)
{
    const int idx = blockIdx.x * 256 + threadIdx.x;
    if (idx >= BDIM * DDIM) return;
    const int b = idx / DDIM;
    float a = 0.0f;
#pragma unroll
    for (int s = 0; s < NSPLIT; s++) a += g_part[(size_t)s * BDIM * DDIM + idx];
    const float tt = t[b] * (1.0f / 999.0f);
    const float sg = 1.0f - tt;
    out[idx] = (a / g_rowsum[b] - x[idx]) / sg;
}

extern "C" void kernel_launch(void* const* d_in, const int* in_sizes, int n_in,
                              void* d_out, int out_size)
{
    const float* xt = (const float*)d_in[0];
    const float* t  = (const float*)d_in[1];
    const float* gt = (const float*)d_in[2];
    float* out = (float*)d_out;

    static int attr_done = 0;
    if (!attr_done) {
        cudaFuncSetAttribute(gemm1_kernel, cudaFuncAttributeMaxDynamicSharedMemorySize, SM1_TOTAL);
        cudaFuncSetAttribute(gemm2_kernel, cudaFuncAttributeMaxDynamicSharedMemorySize, SM2_TOTAL);
        attr_done = 1;
    }

    dim3 g1(NT1, KSPLIT);
    gemm1_kernel<<<g1, 256, SM1_TOTAL>>>(xt, gt);
    softmax_stats_kernel<<<BDIM, 256>>>(t);
    dim3 g2(DT2, NSPLIT);
    gemm2_kernel<<<g2, 256, SM2_TOTAL>>>(gt);
    epilogue_kernel<<<(BDIM * DDIM + 255) / 256, 256>>>(xt, t, out);
}